// round 15
// baseline (speedup 1.0000x reference)
#include <cuda_runtime.h>

#define DTV      0.02f
#define SQRT_DT  0.141421356237309515f
#define SIGMA    0.5f
#define NSTEP    50
#define BATCH    4096
#define PPC      32            // paths per CTA
#define NCTA     (BATCH / PPC) // 128
#define NTHR     384           // 8 Y-warps + 4 q-warps

typedef unsigned long long u64;

// ---- shared-memory layout (float offsets) ----
#define W_IN   0       // [2][64] = 128
#define B_IN   128     // 64
#define W_H    192     // [3][64][64] = 12288
#define B_H    12480   // [3][64] = 192
#define W_OUT  12672   // 64
#define B_OUT  12736   // 1 (+3 pad)
#define NET_SZ 12740
// activations: plain [64 rows][32 paths] floats, 128B rows, NO swizzle
#define ABUF     2048
#define OFF_X0   (2 * NET_SZ)
#define OFF_DX0  (OFF_X0  + ABUF)
#define OFF_X1   (OFF_DX0 + ABUF)
#define OFF_DX1  (OFF_X1  + ABUF)
#define OFF_QX0  (OFF_DX1 + ABUF)
#define OFF_QX1  (OFF_QX0 + ABUF)
#define OFF_HD2  (OFF_QX1 + ABUF)     // DOUBLE buffer: 2 x 192
#define SMEM_FLOATS (OFF_HD2 + 384)
#define SMEM_BYTES  (SMEM_FLOATS * 4)

#define BARY() asm volatile("bar.sync 1, 256;" ::: "memory")
#define BARQ() asm volatile("bar.sync 2, 128;" ::: "memory")

__device__ float g_part[NCTA];
__device__ int   g_count = 0;

__device__ __forceinline__ void cpf(float* d, const float* s, int n, int tid) {
    for (int i = tid; i < n; i += NTHR) d[i] = s[i];
}

__device__ __forceinline__ u64 fma2(u64 a, u64 b, u64 c) {
    u64 d;
    asm("fma.rn.f32x2 %0, %1, %2, %3;" : "=l"(d) : "l"(a), "l"(b), "l"(c));
    return d;
}
__device__ __forceinline__ u64 pk(float lo, float hi) {
    u64 r;
    asm("mov.b64 %0, {%1, %2};" : "=l"(r) : "f"(lo), "f"(hi));
    return r;
}
__device__ __forceinline__ void upk(u64 v, float& lo, float& hi) {
    asm("mov.b64 {%0, %1}, %2;" : "=f"(lo), "=f"(hi) : "l"(v));
}

// ---- team Y hidden layer: h + dh for rows j0, j0+1, paths p0..p0+3 ----
__device__ __forceinline__ void layerY(
    const float* __restrict__ Wy, const float* __restrict__ by,
    const float* __restrict__ X,  const float* __restrict__ DX,
    float* __restrict__ Xn, float* __restrict__ DXn,
    int j0, int p0)
{
    const float2* W2 = (const float2*)Wy;
    const int wj = j0 >> 1;

    u64 h0a = pk(by[j0], by[j0]),         h0b = h0a;
    u64 h1a = pk(by[j0 + 1], by[j0 + 1]), h1b = h1a;
    u64 d0a = 0ull, d0b = 0ull, d1a = 0ull, d1b = 0ull;

#pragma unroll 8
    for (int i = 0; i < 64; i++) {
        float2 w = W2[i * 32 + wj];
        ulonglong2 xv = *(const ulonglong2*)(X  + i * 32 + p0);
        ulonglong2 dv = *(const ulonglong2*)(DX + i * 32 + p0);
        u64 w0 = pk(w.x, w.x);
        u64 w1 = pk(w.y, w.y);
        h0a = fma2(w0, xv.x, h0a); h0b = fma2(w0, xv.y, h0b);
        h1a = fma2(w1, xv.x, h1a); h1b = fma2(w1, xv.y, h1b);
        d0a = fma2(w0, dv.x, d0a); d0b = fma2(w0, dv.y, d0b);
        d1a = fma2(w1, dv.x, d1a); d1b = fma2(w1, dv.y, d1b);
    }

    float h[2][4], d[2][4];
    upk(h0a, h[0][0], h[0][1]); upk(h0b, h[0][2], h[0][3]);
    upk(h1a, h[1][0], h[1][1]); upk(h1b, h[1][2], h[1][3]);
    upk(d0a, d[0][0], d[0][1]); upk(d0b, d[0][2], d[0][3]);
    upk(d1a, d[1][0], d[1][1]); upk(d1b, d[1][2], d[1][3]);
#pragma unroll
    for (int rr = 0; rr < 2; rr++) {
        float s[4], c[4];
#pragma unroll
        for (int p = 0; p < 4; p++) __sincosf(h[rr][p], &s[p], &c[p]);
        *(float4*)(Xn  + (j0 + rr) * 32 + p0) = make_float4(s[0], s[1], s[2], s[3]);
        *(float4*)(DXn + (j0 + rr) * 32 + p0) =
            make_float4(c[0] * d[rr][0], c[1] * d[rr][1],
                        c[2] * d[rr][2], c[3] * d[rr][3]);
    }
}

// ---- team Q hidden layer: q for rows j0..j0+3, paths p0..p0+3 ----
__device__ __forceinline__ void layerQ(
    const float* __restrict__ Wq, const float* __restrict__ bq,
    const float* __restrict__ QX, float* __restrict__ QXn,
    int j0, int p0)
{
    u64 a0a = pk(bq[j0], bq[j0]),         a0b = a0a;
    u64 a1a = pk(bq[j0 + 1], bq[j0 + 1]), a1b = a1a;
    u64 a2a = pk(bq[j0 + 2], bq[j0 + 2]), a2b = a2a;
    u64 a3a = pk(bq[j0 + 3], bq[j0 + 3]), a3b = a3a;

#pragma unroll 8
    for (int i = 0; i < 64; i++) {
        float4 w = *(const float4*)(Wq + i * 64 + j0);
        ulonglong2 qv = *(const ulonglong2*)(QX + i * 32 + p0);
        u64 w0 = pk(w.x, w.x), w1 = pk(w.y, w.y);
        u64 w2 = pk(w.z, w.z), w3 = pk(w.w, w.w);
        a0a = fma2(w0, qv.x, a0a); a0b = fma2(w0, qv.y, a0b);
        a1a = fma2(w1, qv.x, a1a); a1b = fma2(w1, qv.y, a1b);
        a2a = fma2(w2, qv.x, a2a); a2b = fma2(w2, qv.y, a2b);
        a3a = fma2(w3, qv.x, a3a); a3b = fma2(w3, qv.y, a3b);
    }

    u64 aa[4] = {a0a, a1a, a2a, a3a};
    u64 ab[4] = {a0b, a1b, a2b, a3b};
#pragma unroll
    for (int rr = 0; rr < 4; rr++) {
        float v[4];
        upk(aa[rr], v[0], v[1]);
        upk(ab[rr], v[2], v[3]);
#pragma unroll
        for (int p = 0; p < 4; p++) v[p] = __sinf(v[p]);
        *(float4*)(QXn + (j0 + rr) * 32 + p0) = make_float4(v[0], v[1], v[2], v[3]);
    }
}

// Full fused eval on register y state; heads write hdw; ends CTA-synced.
__device__ __forceinline__ void eval_all(float* sm, float tval, float* hdw,
                                         const float yreg[4],
                                         int tid, int wid, int lane)
{
    const float* netY = sm;
    const float* netQ = sm + NET_SZ;
    float* X0  = sm + OFF_X0;
    float* DX0 = sm + OFF_DX0;
    float* X1  = sm + OFF_X1;
    float* DX1 = sm + OFF_DX1;
    float* QX0 = sm + OFF_QX0;
    float* QX1 = sm + OFF_QX1;

    if (tid < 256) {
        // ================= team Y =================
        const int ch = tid & 7, p0c = ch * 4;
#pragma unroll
        for (int k = 0; k < 2; k++) {
            int r = (tid >> 3) + k * 32;
            float wt = netY[W_IN + r], wy = netY[W_IN + 64 + r];
            float tb = fmaf(tval, wt, netY[B_IN + r]);
            float s[4], c[4];
#pragma unroll
            for (int p = 0; p < 4; p++)
                __sincosf(fmaf(yreg[p], wy, tb), &s[p], &c[p]);
            *(float4*)(X0 + r * 32 + p0c) = make_float4(s[0], s[1], s[2], s[3]);
            *(float4*)(DX0 + r * 32 + p0c) =
                make_float4(c[0] * wy, c[1] * wy, c[2] * wy, c[3] * wy);
        }
        BARY();

        const int jsub = lane >> 3, psub = lane & 7;
        const int j0 = wid * 8 + jsub * 2;
        const int p0 = psub * 4;
        layerY(netY + W_H,        netY + B_H,       X0, DX0, X1, DX1, j0, p0);
        BARY();
        layerY(netY + W_H + 4096, netY + B_H + 64,  X1, DX1, X0, DX0, j0, p0);
        BARY();
        layerY(netY + W_H + 8192, netY + B_H + 128, X0, DX0, X1, DX1, j0, p0);
        BARY();

        if (wid < 4) {
            int head = wid >> 1, ih = wid & 1;
            const float* src = head ? DX1 : X1;
            const float* wv  = netY + W_OUT;
            int i0 = ih * 32;
            float a0 = 0.0f, a1 = 0.0f;
#pragma unroll 8
            for (int i = 0; i < 32; i += 2) {
                a0 = fmaf(src[(i0 + i) * 32 + lane],     wv[i0 + i],     a0);
                a1 = fmaf(src[(i0 + i + 1) * 32 + lane], wv[i0 + i + 1], a1);
            }
            hdw[head * 64 + ih * 32 + lane] = a0 + a1;
        }
    } else {
        // ================= team Q =================
        const int qt = tid - 256;
        const int ch = qt & 7, p0c = ch * 4;
#pragma unroll
        for (int k = 0; k < 4; k++) {
            int r = (qt >> 3) + k * 16;
            float wt = netQ[W_IN + r], wy = netQ[W_IN + 64 + r];
            float tb = fmaf(tval, wt, netQ[B_IN + r]);
            float sq[4];
#pragma unroll
            for (int p = 0; p < 4; p++)
                sq[p] = __sinf(fmaf(yreg[p], wy, tb));
            *(float4*)(QX0 + r * 32 + p0c) = make_float4(sq[0], sq[1], sq[2], sq[3]);
        }
        BARQ();

        const int qw = wid - 8;
        const int jsub = lane >> 3, psub = lane & 7;
        const int j0 = qw * 16 + jsub * 4;
        const int p0 = psub * 4;
        layerQ(netQ + W_H,        netQ + B_H,       QX0, QX1, j0, p0);
        BARQ();
        layerQ(netQ + W_H + 4096, netQ + B_H + 64,  QX1, QX0, j0, p0);
        BARQ();
        layerQ(netQ + W_H + 8192, netQ + B_H + 128, QX0, QX1, j0, p0);
        BARQ();

        if (wid < 10) {
            int ih = wid & 1;
            const float* wv = netQ + W_OUT;
            int i0 = ih * 32;
            float a0 = 0.0f, a1 = 0.0f;
#pragma unroll 8
            for (int i = 0; i < 32; i += 2) {
                a0 = fmaf(QX1[(i0 + i) * 32 + lane],     wv[i0 + i],     a0);
                a1 = fmaf(QX1[(i0 + i + 1) * 32 + lane], wv[i0 + i + 1], a1);
            }
            hdw[128 + ih * 32 + lane] = a0 + a1;
        }
    }
    __syncthreads();
}

__global__ __launch_bounds__(NTHR, 1) void fbsnn_main(
    const float* __restrict__ yWin,  const float* __restrict__ yBin,
    const float* __restrict__ yWh,   const float* __restrict__ yBh,
    const float* __restrict__ yWout, const float* __restrict__ yBout,
    const float* __restrict__ qWin,  const float* __restrict__ qBin,
    const float* __restrict__ qWh,   const float* __restrict__ qBh,
    const float* __restrict__ qWout, const float* __restrict__ qBout,
    const float* __restrict__ y0,    const float* __restrict__ dW,
    float* __restrict__ out)
{
    extern __shared__ float sm[];
    const int tid  = threadIdx.x;
    const int wid  = tid >> 5;
    const int lane = tid & 31;

    // ---- stage all weights into smem once ----
    cpf(sm + W_IN,  yWin, 128,   tid);
    cpf(sm + B_IN,  yBin, 64,    tid);
    cpf(sm + W_H,   yWh,  12288, tid);
    cpf(sm + B_H,   yBh,  192,   tid);
    cpf(sm + W_OUT, yWout, 64,   tid);
    if (tid == 0) sm[B_OUT] = yBout[0];
    float* smq = sm + NET_SZ;
    cpf(smq + W_IN,  qWin, 128,   tid);
    cpf(smq + B_IN,  qBin, 64,    tid);
    cpf(smq + W_H,   qWh,  12288, tid);
    cpf(smq + B_H,   qBh,  192,   tid);
    cpf(smq + W_OUT, qWout, 64,   tid);
    if (tid == 0) smq[B_OUT] = qBout[0];
    __syncthreads();

    const int pbase = blockIdx.x * PPC;
    const float ybias = sm[B_OUT];
    const float qbias = smq[B_OUT];

    // per-thread path chunk (4 paths) and register state
    const int ch = (tid < 256 ? tid : tid - 256) & 7;
    const float y0v = y0[0];
    float yreg[4] = {y0v, y0v, y0v, y0v};
    float dwc[4];
#pragma unroll
    for (int j = 0; j < 4; j++) dwc[j] = dW[pbase + ch * 4 + j];

    float ylane = y0v, dwlane = 0.0f;
    float lossAcc = 0.0f, Ytilde = 0.0f;
    if (wid == 0) dwlane = dW[pbase + lane];

    // initial eval at t = 0 -> HD buf0
    eval_all(sm, 0.0f, sm + OFF_HD2, yreg, tid, wid, lane);

    for (int n = 0; n < NSTEP; n++) {
        const float* hdr = sm + OFF_HD2 + (n & 1) * 192;
        float* hdw = sm + OFF_HD2 + ((n + 1) & 1) * 192;

        // per-thread y update from q-head partials (bitwise-identical dup)
#pragma unroll
        for (int j = 0; j < 4; j++) {
            int p = ch * 4 + j;
            float qv = hdr[128 + p] + hdr[160 + p] + qbias;
            yreg[j] += qv * DTV + SIGMA * (SQRT_DT * dwc[j]);
        }
        if (n + 1 < NSTEP) {
#pragma unroll
            for (int j = 0; j < 4; j++)
                dwc[j] = dW[(n + 1) * BATCH + pbase + ch * 4 + j];
        }

        // warp-0 loss bookkeeping (runs concurrently with other warps' eval)
        if (wid == 0) {
            float Yv  = hdr[lane]       + hdr[32 + lane] + ybias;
            float dYv = hdr[64 + lane]  + hdr[96 + lane];
            float ql  = hdr[128 + lane] + hdr[160 + lane] + qbias;
            if (n > 0) {
                float e = Yv - Ytilde;
                lossAcc = fmaf(e, e, lossAcc);
            }
            float dwn = SQRT_DT * dwlane;
            Ytilde = Yv - ql * ql * DTV + SIGMA * dYv * dwn;
            ylane += ql * DTV + SIGMA * dwn;
            if (n + 1 < NSTEP) dwlane = dW[(n + 1) * BATCH + pbase + lane];
        }

        eval_all(sm, (float)(n + 1) * DTV, hdw, yreg, tid, wid, lane);
    }

    if (wid == 0) {
        const float* hdf = sm + OFF_HD2 + (NSTEP & 1) * 192;
        float Yv  = hdf[lane]      + hdf[32 + lane] + ybias;
        float dYv = hdf[64 + lane] + hdf[96 + lane];
        float e = Yv - Ytilde;
        lossAcc = fmaf(e, e, lossAcc);
        float yN = ylane;
        float e1 = Yv - yN * yN;
        float e2 = dYv - 2.0f * yN;
        lossAcc = fmaf(e1, e1, fmaf(e2, e2, lossAcc));
#pragma unroll
        for (int o = 16; o > 0; o >>= 1)
            lossAcc += __shfl_down_sync(0xffffffffu, lossAcc, o);
        if (lane == 0) g_part[blockIdx.x] = lossAcc;
    }

    // ---- last-CTA deterministic reduction (single launch) ----
    if (tid == 0) {
        __threadfence();
        int old = atomicAdd(&g_count, 1);
        if (old == NCTA - 1) {
            __threadfence();
            float acc = 0.0f;
#pragma unroll 8
            for (int i = 0; i < NCTA; i++) acc += g_part[i];
            out[0] = acc * (1.0f / (float)BATCH);
            g_count = 0;
        }
    }
}

extern "C" void kernel_launch(void* const* d_in, const int* in_sizes, int n_in,
                              void* d_out, int out_size)
{
    const float *yWin, *yBin, *yWh, *yBh, *yWout, *yBout;
    const float *qWin, *qBin, *qWh, *qBh, *qWout, *qBout;
    const float *y0, *dW;

    if (in_sizes[0] == 1) {
        y0    = (const float*)d_in[0];
        yWin  = (const float*)d_in[1];
        yBin  = (const float*)d_in[2];
        yWh   = (const float*)d_in[3];
        yBh   = (const float*)d_in[4];
        yWout = (const float*)d_in[5];
        yBout = (const float*)d_in[6];
        qWin  = (const float*)d_in[7];
        qBin  = (const float*)d_in[8];
        qWh   = (const float*)d_in[9];
        qBh   = (const float*)d_in[10];
        qWout = (const float*)d_in[11];
        qBout = (const float*)d_in[12];
        dW    = (const float*)d_in[13];
    } else {
        yWin  = (const float*)d_in[0];
        yBin  = (const float*)d_in[1];
        yWh   = (const float*)d_in[2];
        yBh   = (const float*)d_in[3];
        yWout = (const float*)d_in[4];
        yBout = (const float*)d_in[5];
        qWin  = (const float*)d_in[6];
        qBin  = (const float*)d_in[7];
        qWh   = (const float*)d_in[8];
        qBh   = (const float*)d_in[9];
        qWout = (const float*)d_in[10];
        qBout = (const float*)d_in[11];
        y0    = (const float*)d_in[12];
        dW    = (const float*)d_in[13];
    }

    cudaFuncSetAttribute(fbsnn_main, cudaFuncAttributeMaxDynamicSharedMemorySize,
                         SMEM_BYTES);

    fbsnn_main<<<NCTA, NTHR, SMEM_BYTES>>>(yWin, yBin, yWh, yBh, yWout, yBout,
                                           qWin, qBin, qWh, qBh, qWout, qBout,
                                           y0, dW, (float*)d_out);
}

// round 16
// speedup vs baseline: 1.0096x; 1.0096x over previous
#include <cuda_runtime.h>

#define DTV      0.02f
#define SQRT_DT  0.141421356237309515f
#define SIGMA    0.5f
#define NSTEP    50
#define BATCH    4096
#define PPC      32            // paths per CTA
#define NCTA     (BATCH / PPC) // 128
#define NTHR     256           // 4 Y-warps + 4 q-warps

typedef unsigned long long u64;

// ---- shared-memory layout (float offsets) ----
#define W_IN   0       // [2][64] = 128
#define B_IN   128     // 64
#define W_H    192     // [3][64][64] = 12288
#define B_H    12480   // [3][64] = 192
#define W_OUT  12672   // 64
#define B_OUT  12736   // 1 (+3 pad)
#define NET_SZ 12740
// activations: plain [64 rows][32 paths] floats, 128B rows
#define ABUF     2048
#define OFF_X0   (2 * NET_SZ)
#define OFF_DX0  (OFF_X0  + ABUF)
#define OFF_X1   (OFF_DX0 + ABUF)
#define OFF_DX1  (OFF_X1  + ABUF)
#define OFF_QX0  (OFF_DX1 + ABUF)
#define OFF_QX1  (OFF_QX0 + ABUF)
#define OFF_HD2  (OFF_QX1 + ABUF)     // DOUBLE buffer: 2 x 192
// K-half exchange buffers (u64 rows of 64 slots)
#define OFF_EXA  (OFF_HD2 + 384)      // Y half A gives: [16][64] u64 = 2048 f
#define OFF_EXB  (OFF_EXA + 2048)
#define OFF_EQA  (OFF_EXB + 2048)     // q half A gives: [8][64] u64 = 1024 f
#define OFF_EQB  (OFF_EQA + 1024)
#define SMEM_FLOATS (OFF_EQB + 1024)
#define SMEM_BYTES  (SMEM_FLOATS * 4) // ~176 KB

#define BARY() asm volatile("bar.sync 1, 128;" ::: "memory")
#define BARQ() asm volatile("bar.sync 2, 128;" ::: "memory")

__device__ float g_part[NCTA];
__device__ int   g_count = 0;

__device__ __forceinline__ void cpf(float* d, const float* s, int n, int tid) {
    for (int i = tid; i < n; i += NTHR) d[i] = s[i];
}

__device__ __forceinline__ u64 fma2(u64 a, u64 b, u64 c) {
    u64 d;
    asm("fma.rn.f32x2 %0, %1, %2, %3;" : "=l"(d) : "l"(a), "l"(b), "l"(c));
    return d;
}
__device__ __forceinline__ u64 add2(u64 a, u64 b) {
    u64 d;
    asm("add.rn.f32x2 %0, %1, %2;" : "=l"(d) : "l"(a), "l"(b));
    return d;
}
__device__ __forceinline__ u64 pk(float lo, float hi) {
    u64 r;
    asm("mov.b64 %0, {%1, %2};" : "=l"(r) : "f"(lo), "f"(hi));
    return r;
}
__device__ __forceinline__ void upk(u64 v, float& lo, float& hi) {
    asm("mov.b64 {%0, %1}, %2;" : "=f"(lo), "=f"(hi) : "l"(v));
}

// ---- Y hidden layer, 8j x 4p tile, K-half split + exchange ----
__device__ __forceinline__ void layerY8(
    const float* __restrict__ Wy, const float* __restrict__ by,
    const float* __restrict__ X,  const float* __restrict__ DX,
    float* __restrict__ Xn, float* __restrict__ DXn,
    u64* __restrict__ EXA, u64* __restrict__ EXB,
    int half, int xid, int j0, int p0)
{
    const int ib = half * 32;
    u64 h[8][2], d[8][2];
#pragma unroll
    for (int jj = 0; jj < 8; jj++) {
        h[jj][0] = 0ull; h[jj][1] = 0ull;
        d[jj][0] = 0ull; d[jj][1] = 0ull;
    }

#pragma unroll 4
    for (int k = 0; k < 32; k++) {
        int i = ib + k;
        float4 wA = *(const float4*)(Wy + i * 64 + j0);
        float4 wB = *(const float4*)(Wy + i * 64 + j0 + 4);
        ulonglong2 xv = *(const ulonglong2*)(X  + i * 32 + p0);
        ulonglong2 dv = *(const ulonglong2*)(DX + i * 32 + p0);
        float wv[8] = {wA.x, wA.y, wA.z, wA.w, wB.x, wB.y, wB.z, wB.w};
#pragma unroll
        for (int jj = 0; jj < 8; jj++) {
            u64 w2 = pk(wv[jj], wv[jj]);
            h[jj][0] = fma2(w2, xv.x, h[jj][0]);
            h[jj][1] = fma2(w2, xv.y, h[jj][1]);
            d[jj][0] = fma2(w2, dv.x, d[jj][0]);
            d[jj][1] = fma2(w2, dv.y, d[jj][1]);
        }
    }

    // exchange: A gives jj 4..7, B gives jj 0..3
    {
        u64* EXw = half ? EXB : EXA;
        int give = half ? 0 : 4;
#pragma unroll
        for (int t = 0; t < 4; t++)
#pragma unroll
            for (int pr = 0; pr < 2; pr++) {
                EXw[(t * 2 + pr) * 64 + xid]     = h[give + t][pr];
                EXw[(8 + t * 2 + pr) * 64 + xid] = d[give + t][pr];
            }
    }
    BARY();
    {
        const u64* EXr = half ? EXA : EXB;
        int keep = half ? 4 : 0;
#pragma unroll
        for (int t = 0; t < 4; t++) {
            u64 hh0 = add2(h[keep + t][0], EXr[(t * 2 + 0) * 64 + xid]);
            u64 hh1 = add2(h[keep + t][1], EXr[(t * 2 + 1) * 64 + xid]);
            u64 dd0 = add2(d[keep + t][0], EXr[(8 + t * 2 + 0) * 64 + xid]);
            u64 dd1 = add2(d[keep + t][1], EXr[(8 + t * 2 + 1) * 64 + xid]);
            int r = j0 + keep + t;
            float bv = by[r];
            float hv[4], dv_[4], s[4], c[4];
            upk(hh0, hv[0], hv[1]); upk(hh1, hv[2], hv[3]);
            upk(dd0, dv_[0], dv_[1]); upk(dd1, dv_[2], dv_[3]);
#pragma unroll
            for (int p = 0; p < 4; p++) __sincosf(hv[p] + bv, &s[p], &c[p]);
            *(float4*)(Xn  + r * 32 + p0) = make_float4(s[0], s[1], s[2], s[3]);
            *(float4*)(DXn + r * 32 + p0) =
                make_float4(c[0] * dv_[0], c[1] * dv_[1],
                            c[2] * dv_[2], c[3] * dv_[3]);
        }
    }
    BARY();
}

// ---- q hidden layer, 8j x 4p tile, K-half split + exchange ----
__device__ __forceinline__ void layerQ8(
    const float* __restrict__ Wq, const float* __restrict__ bq,
    const float* __restrict__ QX, float* __restrict__ QXn,
    u64* __restrict__ EQA, u64* __restrict__ EQB,
    int half, int xid, int j0, int p0)
{
    const int ib = half * 32;
    u64 a[8][2];
#pragma unroll
    for (int jj = 0; jj < 8; jj++) { a[jj][0] = 0ull; a[jj][1] = 0ull; }

#pragma unroll 4
    for (int k = 0; k < 32; k++) {
        int i = ib + k;
        float4 wA = *(const float4*)(Wq + i * 64 + j0);
        float4 wB = *(const float4*)(Wq + i * 64 + j0 + 4);
        ulonglong2 qv = *(const ulonglong2*)(QX + i * 32 + p0);
        float wv[8] = {wA.x, wA.y, wA.z, wA.w, wB.x, wB.y, wB.z, wB.w};
#pragma unroll
        for (int jj = 0; jj < 8; jj++) {
            u64 w2 = pk(wv[jj], wv[jj]);
            a[jj][0] = fma2(w2, qv.x, a[jj][0]);
            a[jj][1] = fma2(w2, qv.y, a[jj][1]);
        }
    }

    {
        u64* EQw = half ? EQB : EQA;
        int give = half ? 0 : 4;
#pragma unroll
        for (int t = 0; t < 4; t++)
#pragma unroll
            for (int pr = 0; pr < 2; pr++)
                EQw[(t * 2 + pr) * 64 + xid] = a[give + t][pr];
    }
    BARQ();
    {
        const u64* EQr = half ? EQA : EQB;
        int keep = half ? 4 : 0;
#pragma unroll
        for (int t = 0; t < 4; t++) {
            u64 a0 = add2(a[keep + t][0], EQr[(t * 2 + 0) * 64 + xid]);
            u64 a1 = add2(a[keep + t][1], EQr[(t * 2 + 1) * 64 + xid]);
            int r = j0 + keep + t;
            float bv = bq[r];
            float v[4];
            upk(a0, v[0], v[1]); upk(a1, v[2], v[3]);
#pragma unroll
            for (int p = 0; p < 4; p++) v[p] = __sinf(v[p] + bv);
            *(float4*)(QXn + r * 32 + p0) = make_float4(v[0], v[1], v[2], v[3]);
        }
    }
    BARQ();
}

// Full fused eval on register y state; heads write hdw; ends CTA-synced.
__device__ __forceinline__ void eval_all(float* sm, float tval, float* hdw,
                                         const float yreg[4],
                                         int tid, int wid, int lane)
{
    const float* netY = sm;
    const float* netQ = sm + NET_SZ;
    float* X0  = sm + OFF_X0;
    float* DX0 = sm + OFF_DX0;
    float* X1  = sm + OFF_X1;
    float* DX1 = sm + OFF_DX1;
    float* QX0 = sm + OFF_QX0;
    float* QX1 = sm + OFF_QX1;
    u64* EXA = (u64*)(sm + OFF_EXA);
    u64* EXB = (u64*)(sm + OFF_EXB);
    u64* EQA = (u64*)(sm + OFF_EQA);
    u64* EQB = (u64*)(sm + OFF_EQB);

    if (tid < 128) {
        // ================= team Y =================
        const int ch = tid & 7, p0c = ch * 4;
#pragma unroll
        for (int k = 0; k < 4; k++) {
            int r = (tid >> 3) + k * 16;
            float wt = netY[W_IN + r], wy = netY[W_IN + 64 + r];
            float tb = fmaf(tval, wt, netY[B_IN + r]);
            float s[4], c[4];
#pragma unroll
            for (int p = 0; p < 4; p++)
                __sincosf(fmaf(yreg[p], wy, tb), &s[p], &c[p]);
            *(float4*)(X0 + r * 32 + p0c) = make_float4(s[0], s[1], s[2], s[3]);
            *(float4*)(DX0 + r * 32 + p0c) =
                make_float4(c[0] * wy, c[1] * wy, c[2] * wy, c[3] * wy);
        }
        BARY();

        const int half = tid >> 6;
        const int xid  = tid & 63;
        const int j0 = (xid >> 3) * 8;
        const int p0 = (xid & 7) * 4;
        layerY8(netY + W_H,        netY + B_H,       X0, DX0, X1, DX1,
                EXA, EXB, half, xid, j0, p0);
        layerY8(netY + W_H + 4096, netY + B_H + 64,  X1, DX1, X0, DX0,
                EXA, EXB, half, xid, j0, p0);
        layerY8(netY + W_H + 8192, netY + B_H + 128, X0, DX0, X1, DX1,
                EXA, EXB, half, xid, j0, p0);

        // heads: warps 0-3 = (head Y/dY) x (i-half)
        {
            int head = wid >> 1, ih = wid & 1;
            const float* src = head ? DX1 : X1;
            const float* wv  = netY + W_OUT;
            int i0 = ih * 32;
            float a0 = 0.0f, a1 = 0.0f;
#pragma unroll 8
            for (int i = 0; i < 32; i += 2) {
                a0 = fmaf(src[(i0 + i) * 32 + lane],     wv[i0 + i],     a0);
                a1 = fmaf(src[(i0 + i + 1) * 32 + lane], wv[i0 + i + 1], a1);
            }
            hdw[head * 64 + ih * 32 + lane] = a0 + a1;
        }
    } else {
        // ================= team Q =================
        const int qt = tid - 128;
        const int ch = qt & 7, p0c = ch * 4;
#pragma unroll
        for (int k = 0; k < 4; k++) {
            int r = (qt >> 3) + k * 16;
            float wt = netQ[W_IN + r], wy = netQ[W_IN + 64 + r];
            float tb = fmaf(tval, wt, netQ[B_IN + r]);
            float sq[4];
#pragma unroll
            for (int p = 0; p < 4; p++)
                sq[p] = __sinf(fmaf(yreg[p], wy, tb));
            *(float4*)(QX0 + r * 32 + p0c) = make_float4(sq[0], sq[1], sq[2], sq[3]);
        }
        BARQ();

        const int half = qt >> 6;
        const int xid  = qt & 63;
        const int j0 = (xid >> 3) * 8;
        const int p0 = (xid & 7) * 4;
        layerQ8(netQ + W_H,        netQ + B_H,       QX0, QX1,
                EQA, EQB, half, xid, j0, p0);
        layerQ8(netQ + W_H + 4096, netQ + B_H + 64,  QX1, QX0,
                EQA, EQB, half, xid, j0, p0);
        layerQ8(netQ + W_H + 8192, netQ + B_H + 128, QX0, QX1,
                EQA, EQB, half, xid, j0, p0);

        // q head: warps 4,5 = i-halves
        if (wid < 6) {
            int ih = wid & 1;
            const float* wv = netQ + W_OUT;
            int i0 = ih * 32;
            float a0 = 0.0f, a1 = 0.0f;
#pragma unroll 8
            for (int i = 0; i < 32; i += 2) {
                a0 = fmaf(QX1[(i0 + i) * 32 + lane],     wv[i0 + i],     a0);
                a1 = fmaf(QX1[(i0 + i + 1) * 32 + lane], wv[i0 + i + 1], a1);
            }
            hdw[128 + ih * 32 + lane] = a0 + a1;
        }
    }
    __syncthreads();
}

__global__ __launch_bounds__(NTHR, 1) void fbsnn_main(
    const float* __restrict__ yWin,  const float* __restrict__ yBin,
    const float* __restrict__ yWh,   const float* __restrict__ yBh,
    const float* __restrict__ yWout, const float* __restrict__ yBout,
    const float* __restrict__ qWin,  const float* __restrict__ qBin,
    const float* __restrict__ qWh,   const float* __restrict__ qBh,
    const float* __restrict__ qWout, const float* __restrict__ qBout,
    const float* __restrict__ y0,    const float* __restrict__ dW,
    float* __restrict__ out)
{
    extern __shared__ float sm[];
    const int tid  = threadIdx.x;
    const int wid  = tid >> 5;
    const int lane = tid & 31;

    // ---- stage all weights into smem once ----
    cpf(sm + W_IN,  yWin, 128,   tid);
    cpf(sm + B_IN,  yBin, 64,    tid);
    cpf(sm + W_H,   yWh,  12288, tid);
    cpf(sm + B_H,   yBh,  192,   tid);
    cpf(sm + W_OUT, yWout, 64,   tid);
    if (tid == 0) sm[B_OUT] = yBout[0];
    float* smq = sm + NET_SZ;
    cpf(smq + W_IN,  qWin, 128,   tid);
    cpf(smq + B_IN,  qBin, 64,    tid);
    cpf(smq + W_H,   qWh,  12288, tid);
    cpf(smq + B_H,   qBh,  192,   tid);
    cpf(smq + W_OUT, qWout, 64,   tid);
    if (tid == 0) smq[B_OUT] = qBout[0];
    __syncthreads();

    const int pbase = blockIdx.x * PPC;
    const float ybias = sm[B_OUT];
    const float qbias = smq[B_OUT];

    // per-thread path chunk (4 paths) and register state
    const int ch = (tid < 128 ? tid : tid - 128) & 7;
    const float y0v = y0[0];
    float yreg[4] = {y0v, y0v, y0v, y0v};
    float dwc[4];
#pragma unroll
    for (int j = 0; j < 4; j++) dwc[j] = dW[pbase + ch * 4 + j];

    float ylane = y0v, dwlane = 0.0f;
    float lossAcc = 0.0f, Ytilde = 0.0f;
    if (wid == 0) dwlane = dW[pbase + lane];

    // initial eval at t = 0 -> HD buf0
    eval_all(sm, 0.0f, sm + OFF_HD2, yreg, tid, wid, lane);

    for (int n = 0; n < NSTEP; n++) {
        const float* hdr = sm + OFF_HD2 + (n & 1) * 192;
        float* hdw = sm + OFF_HD2 + ((n + 1) & 1) * 192;

        // per-thread y update from q-head partials (bitwise-identical dup)
#pragma unroll
        for (int j = 0; j < 4; j++) {
            int p = ch * 4 + j;
            float qv = hdr[128 + p] + hdr[160 + p] + qbias;
            yreg[j] += qv * DTV + SIGMA * (SQRT_DT * dwc[j]);
        }
        if (n + 1 < NSTEP) {
#pragma unroll
            for (int j = 0; j < 4; j++)
                dwc[j] = dW[(n + 1) * BATCH + pbase + ch * 4 + j];
        }

        if (wid == 0) {
            float Yv  = hdr[lane]       + hdr[32 + lane] + ybias;
            float dYv = hdr[64 + lane]  + hdr[96 + lane];
            float ql  = hdr[128 + lane] + hdr[160 + lane] + qbias;
            if (n > 0) {
                float e = Yv - Ytilde;
                lossAcc = fmaf(e, e, lossAcc);
            }
            float dwn = SQRT_DT * dwlane;
            Ytilde = Yv - ql * ql * DTV + SIGMA * dYv * dwn;
            ylane += ql * DTV + SIGMA * dwn;
            if (n + 1 < NSTEP) dwlane = dW[(n + 1) * BATCH + pbase + lane];
        }

        eval_all(sm, (float)(n + 1) * DTV, hdw, yreg, tid, wid, lane);
    }

    if (wid == 0) {
        const float* hdf = sm + OFF_HD2 + (NSTEP & 1) * 192;
        float Yv  = hdf[lane]      + hdf[32 + lane] + ybias;
        float dYv = hdf[64 + lane] + hdf[96 + lane];
        float e = Yv - Ytilde;
        lossAcc = fmaf(e, e, lossAcc);
        float yN = ylane;
        float e1 = Yv - yN * yN;
        float e2 = dYv - 2.0f * yN;
        lossAcc = fmaf(e1, e1, fmaf(e2, e2, lossAcc));
#pragma unroll
        for (int o = 16; o > 0; o >>= 1)
            lossAcc += __shfl_down_sync(0xffffffffu, lossAcc, o);
        if (lane == 0) g_part[blockIdx.x] = lossAcc;
    }

    // ---- last-CTA deterministic reduction (single launch) ----
    if (tid == 0) {
        __threadfence();
        int old = atomicAdd(&g_count, 1);
        if (old == NCTA - 1) {
            __threadfence();
            float acc = 0.0f;
#pragma unroll 8
            for (int i = 0; i < NCTA; i++) acc += g_part[i];
            out[0] = acc * (1.0f / (float)BATCH);
            g_count = 0;
        }
    }
}

extern "C" void kernel_launch(void* const* d_in, const int* in_sizes, int n_in,
                              void* d_out, int out_size)
{
    const float *yWin, *yBin, *yWh, *yBh, *yWout, *yBout;
    const float *qWin, *qBin, *qWh, *qBh, *qWout, *qBout;
    const float *y0, *dW;

    if (in_sizes[0] == 1) {
        y0    = (const float*)d_in[0];
        yWin  = (const float*)d_in[1];
        yBin  = (const float*)d_in[2];
        yWh   = (const float*)d_in[3];
        yBh   = (const float*)d_in[4];
        yWout = (const float*)d_in[5];
        yBout = (const float*)d_in[6];
        qWin  = (const float*)d_in[7];
        qBin  = (const float*)d_in[8];
        qWh   = (const float*)d_in[9];
        qBh   = (const float*)d_in[10];
        qWout = (const float*)d_in[11];
        qBout = (const float*)d_in[12];
        dW    = (const float*)d_in[13];
    } else {
        yWin  = (const float*)d_in[0];
        yBin  = (const float*)d_in[1];
        yWh   = (const float*)d_in[2];
        yBh   = (const float*)d_in[3];
        yWout = (const float*)d_in[4];
        yBout = (const float*)d_in[5];
        qWin  = (const float*)d_in[6];
        qBin  = (const float*)d_in[7];
        qWh   = (const float*)d_in[8];
        qBh   = (const float*)d_in[9];
        qWout = (const float*)d_in[10];
        qBout = (const float*)d_in[11];
        y0    = (const float*)d_in[12];
        dW    = (const float*)d_in[13];
    }

    cudaFuncSetAttribute(fbsnn_main, cudaFuncAttributeMaxDynamicSharedMemorySize,
                         SMEM_BYTES);

    fbsnn_main<<<NCTA, NTHR, SMEM_BYTES>>>(yWin, yBin, yWh, yBh, yWout, yBout,
                                           qWin, qBin, qWh, qBh, qWout, qBout,
                                           y0, dW, (float*)d_out);
}